// round 3
// baseline (speedup 1.0000x reference)
#include <cuda_runtime.h>
#include <math.h>

#define LDIM 1024
#define BDIM 4
#define STEPS 16
#define RPB 8  // rows per block in step kernel

// Scratch (allocation-free rule: __device__ globals)
__device__ float g_Us[(size_t)BDIM * LDIM * LDIM];
__device__ float g_Ahat[(size_t)BDIM * LDIM * LDIM];
__device__ float g_rs[BDIM * LDIM];
__device__ float g_cs[BDIM * LDIM];
__device__ float g_Lm[BDIM * LDIM];
__device__ float g_c[BDIM * LDIM];

// ---------------------------------------------------------------------------
// Zero row/col accumulators (idempotent; start of every launch)
// ---------------------------------------------------------------------------
__global__ void zero_kernel() {
    int i = blockIdx.x * blockDim.x + threadIdx.x;
    if (i < BDIM * LDIM) { g_rs[i] = 0.f; g_cs[i] = 0.f; }
}

// ---------------------------------------------------------------------------
// Init: Us = 0.5*(x + x^T) - s ; accumulate rs/cs of x .* M
// grid (32, 32, 4), block (32, 8); 32x32 tiles, 4 rows/thread
// ---------------------------------------------------------------------------
__global__ void init_kernel(const float* __restrict__ x,
                            const float* __restrict__ M,
                            const float* __restrict__ s_p) {
    __shared__ float t2[32][33];
    int b = blockIdx.z;
    int tx = blockIdx.x, ty = blockIdx.y;
    int c = threadIdx.x;
    int r0 = threadIdx.y * 4;
    float s = s_p[0];
    const float* xb = x + (size_t)b * LDIM * LDIM;
    const float* mb = M + (size_t)b * LDIM * LDIM;

    // partner tile: x[b, tx*32 + r, ty*32 + c]
#pragma unroll
    for (int k = 0; k < 4; k++) {
        int r = r0 + k;
        t2[r][c] = xb[(size_t)(tx * 32 + r) * LDIM + ty * 32 + c];
    }
    __syncthreads();

    float colsum = 0.f;
#pragma unroll
    for (int k = 0; k < 4; k++) {
        int r = r0 + k;
        int gi = ty * 32 + r;
        int gj = tx * 32 + c;
        size_t idx = (size_t)gi * LDIM + gj;
        float xv = xb[idx];
        float us = 0.5f * (xv + t2[c][r]) - s;
        g_Us[(size_t)b * LDIM * LDIM + idx] = us;
        float am = xv * mb[idx];
        // row partial: reduce across the 32 lanes of this warp-row
        float rp = am;
#pragma unroll
        for (int o = 16; o > 0; o >>= 1) rp += __shfl_down_sync(0xffffffffu, rp, o);
        if (c == 0) atomicAdd(&g_rs[b * LDIM + gi], rp);
        colsum += am;
    }
    atomicAdd(&g_cs[b * LDIM + tx * 32 + c], colsum);
}

// ---------------------------------------------------------------------------
// Lm / c update.  init_flag=1: Lm = w*relu(r). else Lm += belt*lr_belt^t*relu(r)
// r = 0.5*(rs+cs) - 1 ; c = Lm * sign(r) ; zero rs/cs for next step.
// ---------------------------------------------------------------------------
__global__ void lm_kernel(const float* __restrict__ w_p,
                          const float* __restrict__ belt_p,
                          const float* __restrict__ lrb_p,
                          int t, int init_flag) {
    int i = blockIdx.x * blockDim.x + threadIdx.x;
    if (i >= BDIM * LDIM) return;
    float r = 0.5f * (g_rs[i] + g_cs[i]) - 1.0f;
    float pr = fmaxf(r, 0.f);
    float lm;
    if (init_flag) {
        lm = w_p[0] * pr;
    } else {
        lm = g_Lm[i] + belt_p[0] * powf(lrb_p[0], (float)t) * pr;
    }
    g_Lm[i] = lm;
    float sgn = (r > 0.f) ? 1.f : ((r < 0.f) ? -1.f : 0.f);
    g_c[i] = lm * sgn;
    g_rs[i] = 0.f;
    g_cs[i] = 0.f;
}

// ---------------------------------------------------------------------------
// Step kernel (elementwise update + fused row/col reduction).
// grid (LDIM/RPB, BDIM), block 256. Each block covers RPB full rows.
// Thread tid handles columns [4*tid, 4*tid+4).
// use_x=1: read A_hat from x (t==0), else from g_Ahat.
// ---------------------------------------------------------------------------
__global__ void __launch_bounds__(256)
step_kernel(const float* __restrict__ x,
            const float* __restrict__ M,
            const float* __restrict__ rho,
            const float* __restrict__ alpha_p,
            const float* __restrict__ lra_p,
            int t, int use_x) {
    int b = blockIdx.y;
    int row0 = blockIdx.x * RPB;
    int tid = threadIdx.x;
    int wid = tid >> 5, lane = tid & 31;
    int j0 = tid * 4;

    const float* Ain = use_x ? x : (const float*)g_Ahat;
    float* Aout = g_Ahat;

    float at = alpha_p[0] * powf(lra_p[0], (float)t);

    size_t baseB = (size_t)b * LDIM * LDIM;
    float4 cj = *(const float4*)&g_c[b * LDIM + j0];
    float ca0 = 0.f, ca1 = 0.f, ca2 = 0.f, ca3 = 0.f;

    __shared__ float srow[8][RPB];

#pragma unroll
    for (int r = 0; r < RPB; r++) {
        int row = row0 + r;
        size_t base = baseB + (size_t)row * LDIM + j0;
        float4 ah = *(const float4*)(Ain + base);
        float4 m  = *(const float4*)(M + base);
        float4 us = *(const float4*)(g_Us + base);
        float4 rp = *(const float4*)(rho + (size_t)row * LDIM + j0);
        float ci = g_c[b * LDIM + row];

        float rowp = 0.f;
        float4 ov;

        {
            float g = us.x - ci - cj.x;
            float v = ah.x + at * ah.x * m.x * g;
            float sv = fminf(fmaxf(fabsf(v) - rp.x * at, 0.f), 1.f);
            ov.x = sv; float am = sv * m.x; rowp += am; ca0 += am;
        }
        {
            float g = us.y - ci - cj.y;
            float v = ah.y + at * ah.y * m.y * g;
            float sv = fminf(fmaxf(fabsf(v) - rp.y * at, 0.f), 1.f);
            ov.y = sv; float am = sv * m.y; rowp += am; ca1 += am;
        }
        {
            float g = us.z - ci - cj.z;
            float v = ah.z + at * ah.z * m.z * g;
            float sv = fminf(fmaxf(fabsf(v) - rp.z * at, 0.f), 1.f);
            ov.z = sv; float am = sv * m.z; rowp += am; ca2 += am;
        }
        {
            float g = us.w - ci - cj.w;
            float v = ah.w + at * ah.w * m.w * g;
            float sv = fminf(fmaxf(fabsf(v) - rp.w * at, 0.f), 1.f);
            ov.w = sv; float am = sv * m.w; rowp += am; ca3 += am;
        }
        *(float4*)(Aout + base) = ov;

#pragma unroll
        for (int o = 16; o > 0; o >>= 1) rowp += __shfl_down_sync(0xffffffffu, rowp, o);
        if (lane == 0) srow[wid][r] = rowp;
    }
    __syncthreads();
    if (tid < RPB) {
        float s = 0.f;
#pragma unroll
        for (int w = 0; w < 8; w++) s += srow[w][tid];
        g_rs[b * LDIM + row0 + tid] = s;  // block covers full row: direct store
    }
    atomicAdd(&g_cs[b * LDIM + j0 + 0], ca0);
    atomicAdd(&g_cs[b * LDIM + j0 + 1], ca1);
    atomicAdd(&g_cs[b * LDIM + j0 + 2], ca2);
    atomicAdd(&g_cs[b * LDIM + j0 + 3], ca3);
}

// ---------------------------------------------------------------------------
// Final: out = 0.5*(Ahat + Ahat^T) .* M   (tiled transpose)
// ---------------------------------------------------------------------------
__global__ void final_kernel(const float* __restrict__ M, float* __restrict__ out) {
    __shared__ float t2[32][33];
    int b = blockIdx.z;
    int tx = blockIdx.x, ty = blockIdx.y;
    int c = threadIdx.x;
    int r0 = threadIdx.y * 4;
    const float* ab = g_Ahat + (size_t)b * LDIM * LDIM;
    const float* mb = M + (size_t)b * LDIM * LDIM;
    float* ob = out + (size_t)b * LDIM * LDIM;

#pragma unroll
    for (int k = 0; k < 4; k++) {
        int r = r0 + k;
        t2[r][c] = ab[(size_t)(tx * 32 + r) * LDIM + ty * 32 + c];
    }
    __syncthreads();
#pragma unroll
    for (int k = 0; k < 4; k++) {
        int r = r0 + k;
        int gi = ty * 32 + r;
        int gj = tx * 32 + c;
        size_t idx = (size_t)gi * LDIM + gj;
        ob[idx] = 0.5f * (ab[idx] + t2[c][r]) * mb[idx];
    }
}

// ---------------------------------------------------------------------------
extern "C" void kernel_launch(void* const* d_in, const int* in_sizes, int n_in,
                              void* d_out, int out_size) {
    const float* x     = (const float*)d_in[0];
    const float* M     = (const float*)d_in[1];
    const float* s_p   = (const float*)d_in[2];
    const float* w_p   = (const float*)d_in[3];
    const float* rho_p = (const float*)d_in[4];
    const float* alpha_p = (const float*)d_in[5];
    const float* belt_p  = (const float*)d_in[6];
    const float* lra_p   = (const float*)d_in[7];
    const float* lrb_p   = (const float*)d_in[8];
    float* out = (float*)d_out;

    // 1. zero accumulators
    zero_kernel<<<(BDIM * LDIM + 255) / 256, 256>>>();

    // 2. init: Us, rs/cs of x.*M
    dim3 tgrid(LDIM / 32, LDIM / 32, BDIM);
    dim3 tblk(32, 8);
    init_kernel<<<tgrid, tblk>>>(x, M, s_p);

    // 3. Lm0, c0
    lm_kernel<<<(BDIM * LDIM + 255) / 256, 256>>>(w_p, belt_p, lrb_p, 0, 1);

    // 4. main loop
    dim3 sgrid(LDIM / RPB, BDIM);
    for (int t = 0; t < STEPS; t++) {
        step_kernel<<<sgrid, 256>>>(x, M, rho_p, alpha_p, lra_p, t, t == 0 ? 1 : 0);
        lm_kernel<<<(BDIM * LDIM + 255) / 256, 256>>>(w_p, belt_p, lrb_p, t, 0);
    }

    // 5. output symmetrize
    final_kernel<<<tgrid, tblk>>>(M, out);
}